// round 11
// baseline (speedup 1.0000x reference)
#include <cuda_runtime.h>

// Problem constants
#define Tn 336
#define Fn 12
#define Hn 50
#define Bn 4096
#define BC 32          // batch rows per CTA
#define NTHREADS 512
#define RPG 4          // rows per group (8 groups x 2 warps)
#define HPAD 52        // non-dup h2 row stride (floats)
#define HDUP 100       // duplicated h row stride (floats): [h0,h0,h1,h1,...]

// shared memory float offsets (weights in [j][u][4-gates] layout, 16B per (j,u))
#define W0H_OFF 0        // layer0 recurrent  [50][50][4] = 10000
#define W1I_OFF 10000    // layer1 input(h0)
#define W1R_OFF 20000    // layer1 recurrent(h1)
#define W2I_OFF 30000    // layer2 input(h1)
#define W2R_OFF 40000    // layer2 recurrent(h2)
#define HD0_OFF 50000    // h0 duplicated: 32*100 = 3200
#define HD1_OFF 53200    // h1 duplicated: 3200
#define HS2_OFF 56400    // h2 normal: 32*52 = 1664
#define SMEM_FLOATS 58064
#define SMEM_BYTES (SMEM_FLOATS * 4)   // 232,256 <= 232,448

#define BT (Bn * Tn)   // 1,376,256

// precomputed layer-0 input projection (+bias), [bt][u][4 gates i,f,g,o]
// +512 pad: harmless over-prefetch on the final timestep
__device__ float g_xz0[(size_t)BT * 200 + 512];

typedef unsigned long long u64;

// packed dual-fp32 FMA (sm_103a FFMA2)
__device__ __forceinline__ void ffma2(u64& z, const u64 w, const u64 h) {
    asm("fma.rn.f32x2 %0, %1, %2, %0;" : "+l"(z) : "l"(w), "l"(h));
}
__device__ __forceinline__ u64 dup2(const float s) {
    u64 r; asm("mov.b64 %0, {%1, %1};" : "=l"(r) : "f"(s)); return r;
}
__device__ __forceinline__ u64 pack2(const float lo, const float hi) {
    u64 r; asm("mov.b64 %0, {%1, %2};" : "=l"(r) : "f"(lo), "f"(hi)); return r;
}
__device__ __forceinline__ void unpack2(const u64 v, float& lo, float& hi) {
    asm("mov.b64 {%0, %1}, %2;" : "=f"(lo), "=f"(hi) : "l"(v));
}

__device__ __forceinline__ float sigmoidf_(float v) {
    return 1.0f / (1.0f + __expf(-v));
}
__device__ __forceinline__ float tanhf_(float v) {
    const float e = __expf(2.0f * v);
    return 1.0f - 2.0f / (e + 1.0f);
}

// named barrier for a 2-warp group (ids 1..8)
__device__ __forceinline__ void barg(int id) {
    asm volatile("bar.sync %0, 64;" :: "r"(id) : "memory");
}

struct Z2 { u64 a, b; };   // a = (i,f), b = (g,o)

// z += sum_{j<50} W[j][u][:] * h[j], h from DUPLICATED storage (stride HDUP).
// Weight loads double-buffered: block jb+1's LDS issued before block jb's FMAs.
__device__ __forceinline__ void accD(Z2 z[RPG], const float* __restrict__ W,
                                     const float* __restrict__ hd, int u)
{
    const float* w  = W + u*4;
    const float* hq = hd;
    ulonglong2 a0 = *(const ulonglong2*)(w);
    ulonglong2 a1 = *(const ulonglong2*)(w + 200);
    ulonglong2 a2 = *(const ulonglong2*)(w + 400);
    ulonglong2 a3 = *(const ulonglong2*)(w + 600);
#pragma unroll 1
    for (int jb = 0; jb < 48; jb += 4) {
        const ulonglong2 n0 = *(const ulonglong2*)(w + 800);
        const ulonglong2 n1 = *(const ulonglong2*)(w + 1000);
        const ulonglong2 n2 = *(const ulonglong2*)(w + 1200);   // benign over-read in smem
        const ulonglong2 n3 = *(const ulonglong2*)(w + 1400);
#pragma unroll
        for (int r = 0; r < RPG; r++) {
            const ulonglong2 d01 = *(const ulonglong2*)(hq + r*HDUP);      // (hj,hj),(hj1,hj1)
            const ulonglong2 d23 = *(const ulonglong2*)(hq + r*HDUP + 4);
            ffma2(z[r].a, a0.x, d01.x); ffma2(z[r].b, a0.y, d01.x);
            ffma2(z[r].a, a1.x, d01.y); ffma2(z[r].b, a1.y, d01.y);
            ffma2(z[r].a, a2.x, d23.x); ffma2(z[r].b, a2.y, d23.x);
            ffma2(z[r].a, a3.x, d23.y); ffma2(z[r].b, a3.y, d23.y);
        }
        a0 = n0; a1 = n1; a2 = n2; a3 = n3;
        w += 800; hq += 8;
    }
    // remainder j = 48,49: weights already prefetched into a0,a1; hq at +96
#pragma unroll
    for (int r = 0; r < RPG; r++) {
        const ulonglong2 d01 = *(const ulonglong2*)(hq + r*HDUP);
        ffma2(z[r].a, a0.x, d01.x); ffma2(z[r].b, a0.y, d01.x);
        ffma2(z[r].a, a1.x, d01.y); ffma2(z[r].b, a1.y, d01.y);
    }
}

// same, h from NORMAL storage (stride HPAD), dup2 in regs
__device__ __forceinline__ void accR(Z2 z[RPG], const float* __restrict__ W,
                                     const float* __restrict__ hb, int u)
{
    const float* w  = W + u*4;
    const float* hq = hb;
    ulonglong2 a0 = *(const ulonglong2*)(w);
    ulonglong2 a1 = *(const ulonglong2*)(w + 200);
    ulonglong2 a2 = *(const ulonglong2*)(w + 400);
    ulonglong2 a3 = *(const ulonglong2*)(w + 600);
#pragma unroll 1
    for (int jb = 0; jb < 48; jb += 4) {
        const ulonglong2 n0 = *(const ulonglong2*)(w + 800);
        const ulonglong2 n1 = *(const ulonglong2*)(w + 1000);
        const ulonglong2 n2 = *(const ulonglong2*)(w + 1200);
        const ulonglong2 n3 = *(const ulonglong2*)(w + 1400);
#pragma unroll
        for (int r = 0; r < RPG; r++) {
            const float4 hv = *(const float4*)(hq + r*HPAD);
            const u64 h0 = dup2(hv.x);
            const u64 h1 = dup2(hv.y);
            const u64 h2 = dup2(hv.z);
            const u64 h3 = dup2(hv.w);
            ffma2(z[r].a, a0.x, h0); ffma2(z[r].b, a0.y, h0);
            ffma2(z[r].a, a1.x, h1); ffma2(z[r].b, a1.y, h1);
            ffma2(z[r].a, a2.x, h2); ffma2(z[r].b, a2.y, h2);
            ffma2(z[r].a, a3.x, h3); ffma2(z[r].b, a3.y, h3);
        }
        a0 = n0; a1 = n1; a2 = n2; a3 = n3;
        w += 800; hq += 4;   // NORMAL storage: 4 floats per 4 j's
    }
    // remainder j = 48,49 (hq at +48)
#pragma unroll
    for (int r = 0; r < RPG; r++) {
        const u64 h48 = dup2(hq[r*HPAD]);
        const u64 h49 = dup2(hq[r*HPAD + 1]);
        ffma2(z[r].a, a0.x, h48); ffma2(z[r].b, a0.y, h48);
        ffma2(z[r].a, a1.x, h49); ffma2(z[r].b, a1.y, h49);
    }
}

// =================== precompute: xz0 = x @ Wih0^T + (bih0 + bhh0) ===================
// tiled: block of 128 threads handles 128 bt rows; weights register-resident;
// x tile staged via smem; stores fully coalesced.
#define XPB 128
__global__ void __launch_bounds__(XPB, 8)
xproj_kernel(const float* __restrict__ x, const float* __restrict__ Wih0,
             const float* __restrict__ bih0, const float* __restrict__ bhh0)
{
    __shared__ float4 xsm[XPB * 3];    // 128 bt x 12 floats
    const int tid = threadIdx.x;
    const long long btbase = (long long)blockIdx.x * XPB;

    {   // cooperative x tile load (coalesced float4)
        const float4* xg = (const float4*)(x + btbase * 12);
        for (int i = tid; i < XPB * 3; i += XPB) xsm[i] = xg[i];
    }

    // thread owns output columns tid and tid+128 (second only if < 200)
    float w0[12], w1[12], b0, b1 = 0.f;
    {
        const int col = tid;               // 0..127
        const int g = col & 3, uu = col >> 2;
#pragma unroll
        for (int k = 0; k < 12; k++) w0[k] = Wih0[(g*50 + uu)*12 + k];
        b0 = bih0[g*50 + uu] + bhh0[g*50 + uu];
        const int col2 = tid + XPB;        // 128..255
        if (col2 < 200) {
            const int g2 = col2 & 3, u2 = col2 >> 2;
#pragma unroll
            for (int k = 0; k < 12; k++) w1[k] = Wih0[(g2*50 + u2)*12 + k];
            b1 = bih0[g2*50 + u2] + bhh0[g2*50 + u2];
        }
    }
    __syncthreads();

    float* outp = g_xz0 + (size_t)btbase * 200;
    const bool two = (tid + XPB) < 200;
#pragma unroll 1
    for (int b = 0; b < XPB; b++) {
        const float4 x0 = xsm[b*3], x1 = xsm[b*3 + 1], x2 = xsm[b*3 + 2];
        float s0 = b0, s1 = b1;
        s0 += w0[0]*x0.x + w0[1]*x0.y + w0[2]*x0.z  + w0[3]*x0.w;
        s0 += w0[4]*x1.x + w0[5]*x1.y + w0[6]*x1.z  + w0[7]*x1.w;
        s0 += w0[8]*x2.x + w0[9]*x2.y + w0[10]*x2.z + w0[11]*x2.w;
        s1 += w1[0]*x0.x + w1[1]*x0.y + w1[2]*x0.z  + w1[3]*x0.w;
        s1 += w1[4]*x1.x + w1[5]*x1.y + w1[6]*x1.z  + w1[7]*x1.w;
        s1 += w1[8]*x2.x + w1[9]*x2.y + w1[10]*x2.z + w1[11]*x2.w;
        outp[b*200 + tid] = s0;
        if (two) outp[b*200 + tid + XPB] = s1;
    }
}

// =================== main fused LSTM ===================
__global__ void __launch_bounds__(NTHREADS, 1)
lstm_fused(const float* __restrict__ Whh0,
           const float* __restrict__ Wih1, const float* __restrict__ Whh1,
           const float* __restrict__ bih1, const float* __restrict__ bhh1,
           const float* __restrict__ Wih2, const float* __restrict__ Whh2,
           const float* __restrict__ bih2, const float* __restrict__ bhh2,
           const float* __restrict__ Wlin, const float* __restrict__ blin,
           float* __restrict__ out)
{
    extern __shared__ float sm[];

    const int tid   = threadIdx.x;
    const int lane  = tid & 31;
    const int wid   = tid >> 5;
    const int grp   = wid >> 1;               // 0..7
    const int bid   = grp + 1;                // named barrier id
    const int r0    = grp * RPG;              // row base (4 rows)
    const int u     = (wid & 1) * 32 + lane;  // unit id
    const bool act  = (u < Hn);

    // ---- stage weights: [j][u][4 gates] ----
    {
        const float* srcs[5] = { Whh0, Wih1, Whh1, Wih2, Whh2 };
        const int offs[5] = { W0H_OFF, W1I_OFF, W1R_OFF, W2I_OFF, W2R_OFF };
#pragma unroll 1
        for (int s = 0; s < 5; s++) {
            const float* Wsrc = srcs[s];
            float* A = sm + offs[s];
            for (int idx = tid; idx < 10000; idx += NTHREADS) {
                const int g  = idx & 3;
                const int uu = (idx >> 2) % 50;
                const int j  = idx / 200;
                A[idx] = Wsrc[(g*50 + uu)*50 + j];
            }
        }
    }
    // zero all h state (dup + normal)
    for (int idx = tid; idx < SMEM_FLOATS - HD0_OFF; idx += NTHREADS)
        sm[HD0_OFF + idx] = 0.0f;

    // biases for layers 1,2 as packed z inits
    u64 b1a = 0, b1b = 0, b2a = 0, b2b = 0;
    if (act) {
        b1a = pack2(bih1[u]       + bhh1[u],       bih1[50 + u]  + bhh1[50 + u]);
        b1b = pack2(bih1[100 + u] + bhh1[100 + u], bih1[150 + u] + bhh1[150 + u]);
        b2a = pack2(bih2[u]       + bhh2[u],       bih2[50 + u]  + bhh2[50 + u]);
        b2b = pack2(bih2[100 + u] + bhh2[100 + u], bih2[150 + u] + bhh2[150 + u]);
    }

    float c0[RPG], c1[RPG], c2[RPG];
#pragma unroll
    for (int r = 0; r < RPG; r++) { c0[r] = 0.f; c1[r] = 0.f; c2[r] = 0.f; }

    const long long bbase = (long long)blockIdx.x * BC;
    const float* xz = g_xz0 + ((size_t)(bbase + r0) * Tn) * 200 + (size_t)u * 4;

    // prefetch xz for t=0
    ulonglong2 pf[RPG];
    if (act) {
#pragma unroll
        for (int r = 0; r < RPG; r++)
            pf[r] = *(const ulonglong2*)(xz + (size_t)r * (Tn*200));
    }

    __syncthreads();

    float* HD0 = sm + HD0_OFF + r0*HDUP;
    float* HD1 = sm + HD1_OFF + r0*HDUP;
    float* HS2 = sm + HS2_OFF + r0*HPAD;

    for (int t = 0; t < Tn; t++) {
        float hn[RPG];
        Z2 z[RPG];

        // ================= layer 0 =================
        if (act) {
            // consume prefetched x-projection, then immediately prefetch t+1
#pragma unroll
            for (int r = 0; r < RPG; r++) { z[r].a = pf[r].x; z[r].b = pf[r].y; }
            xz += 200;
#pragma unroll
            for (int r = 0; r < RPG; r++)
                pf[r] = *(const ulonglong2*)(xz + (size_t)r * (Tn*200));  // pad covers last t
            accD(z, sm + W0H_OFF, HD0, u);
#pragma unroll
            for (int r = 0; r < RPG; r++) {
                float zi, zf, zg, zo;
                unpack2(z[r].a, zi, zf);
                unpack2(z[r].b, zg, zo);
                const float ig = sigmoidf_(zi);
                const float fg = sigmoidf_(zf);
                const float gg = tanhf_(zg);
                const float og = sigmoidf_(zo);
                c0[r] = fg * c0[r] + ig * gg;
                hn[r] = og * tanhf_(c0[r]);
            }
        }
        barg(bid);
        if (act) {
#pragma unroll
            for (int r = 0; r < RPG; r++)
                *(float2*)(HD0 + r*HDUP + 2*u) = make_float2(hn[r], hn[r]);
        }
        barg(bid);

        // ================= layer 1 =================
        if (act) {
#pragma unroll
            for (int r = 0; r < RPG; r++) { z[r].a = b1a; z[r].b = b1b; }
            accD(z, sm + W1I_OFF, HD0, u);
            accD(z, sm + W1R_OFF, HD1, u);
#pragma unroll
            for (int r = 0; r < RPG; r++) {
                float zi, zf, zg, zo;
                unpack2(z[r].a, zi, zf);
                unpack2(z[r].b, zg, zo);
                const float ig = sigmoidf_(zi);
                const float fg = sigmoidf_(zf);
                const float gg = tanhf_(zg);
                const float og = sigmoidf_(zo);
                c1[r] = fg * c1[r] + ig * gg;
                hn[r] = og * tanhf_(c1[r]);
            }
        }
        barg(bid);
        if (act) {
#pragma unroll
            for (int r = 0; r < RPG; r++)
                *(float2*)(HD1 + r*HDUP + 2*u) = make_float2(hn[r], hn[r]);
        }
        barg(bid);

        // ================= layer 2 =================
        if (act) {
#pragma unroll
            for (int r = 0; r < RPG; r++) { z[r].a = b2a; z[r].b = b2b; }
            accD(z, sm + W2I_OFF, HD1, u);
            accR(z, sm + W2R_OFF, HS2, u);
#pragma unroll
            for (int r = 0; r < RPG; r++) {
                float zi, zf, zg, zo;
                unpack2(z[r].a, zi, zf);
                unpack2(z[r].b, zg, zo);
                const float ig = sigmoidf_(zi);
                const float fg = sigmoidf_(zf);
                const float gg = tanhf_(zg);
                const float og = sigmoidf_(zo);
                c2[r] = fg * c2[r] + ig * gg;
                hn[r] = og * tanhf_(c2[r]);
            }
        }
        barg(bid);
        if (act) {
#pragma unroll
            for (int r = 0; r < RPG; r++) HS2[r*HPAD + u] = hn[r];
        }
        barg(bid);
    }

    __syncthreads();

    // ---- final linear: out[b] = h2[b] . Wlin + blin ----
    if (tid < BC) {
        float s = blin[0];
#pragma unroll 10
        for (int uu = 0; uu < Hn; uu++)
            s += sm[HS2_OFF + tid*HPAD + uu] * Wlin[uu];
        out[bbase + tid] = s;
    }
}

extern "C" void kernel_launch(void* const* d_in, const int* in_sizes, int n_in,
                              void* d_out, int out_size)
{
    (void)in_sizes; (void)n_in; (void)out_size;
    const float* x    = (const float*)d_in[0];
    const float* Wih0 = (const float*)d_in[1];
    const float* Whh0 = (const float*)d_in[2];
    const float* bih0 = (const float*)d_in[3];
    const float* bhh0 = (const float*)d_in[4];
    const float* Wih1 = (const float*)d_in[5];
    const float* Whh1 = (const float*)d_in[6];
    const float* bih1 = (const float*)d_in[7];
    const float* bhh1 = (const float*)d_in[8];
    const float* Wih2 = (const float*)d_in[9];
    const float* Whh2 = (const float*)d_in[10];
    const float* bih2 = (const float*)d_in[11];
    const float* bhh2 = (const float*)d_in[12];
    const float* Wlin = (const float*)d_in[13];
    const float* blin = (const float*)d_in[14];
    float* out = (float*)d_out;

    xproj_kernel<<<BT / XPB, XPB>>>(x, Wih0, bih0, bhh0);

    cudaFuncSetAttribute(lstm_fused, cudaFuncAttributeMaxDynamicSharedMemorySize, SMEM_BYTES);
    lstm_fused<<<Bn / BC, NTHREADS, SMEM_BYTES>>>(
        Whh0,
        Wih1, Whh1, bih1, bhh1,
        Wih2, Whh2, bih2, bhh2,
        Wlin, blin, out);
}